// round 5
// baseline (speedup 1.0000x reference)
#include <cuda_runtime.h>
#include <math.h>
#include <stdint.h>

// Problem constants
#define DIM    1024
#define BATCH  1024
#define KSET   128
#define N_MEM  100000

// ---------------- device scratch (no allocations allowed) ----------------
__device__ float g_h[BATCH * DIM];         // hidden after GELU (4 MB)
__device__ float g_q[BATCH * DIM];         // queries (4 MB)

// =========================================================================
// 3xTF32 tensor-core GEMM (NT): C = act(A[M,K] @ B[N,K]^T + bias)
// mma.sync.m16n8k8 tf32, fp32 operands split hi/lo for near-fp32 accuracy.
// BM=128, BN=64, BK=16, 256 threads (8 warps as 4m x 2n, warp tile 32x32).
// Fused epilogue: +bias (and exact GELU for layer 1). No partial buffers.
// Output target (g_h or g_q) selected by template to keep kernel_launch
// free of any host API besides kernel launches (graph-capture safety).
// =========================================================================
__device__ __forceinline__ void split_tf32(float x, uint32_t& hi, uint32_t& lo)
{
    asm("cvt.rna.tf32.f32 %0, %1;" : "=r"(hi) : "f"(x));
    float r = x - __uint_as_float(hi);
    asm("cvt.rna.tf32.f32 %0, %1;" : "=r"(lo) : "f"(r));
}

__device__ __forceinline__ void mma_tf32(float* d,
                                         uint32_t a0, uint32_t a1,
                                         uint32_t a2, uint32_t a3,
                                         uint32_t b0, uint32_t b1)
{
    asm volatile(
        "mma.sync.aligned.m16n8k8.row.col.f32.tf32.tf32.f32 "
        "{%0,%1,%2,%3}, {%4,%5,%6,%7}, {%8,%9}, {%0,%1,%2,%3};"
        : "+f"(d[0]), "+f"(d[1]), "+f"(d[2]), "+f"(d[3])
        : "r"(a0), "r"(a1), "r"(a2), "r"(a3), "r"(b0), "r"(b1));
}

__device__ __forceinline__ float gelu_exact(float x) {
    return 0.5f * x * (1.0f + erff(x * 0.70710678118654752f));
}

#define ASTRIDE 136   // BM + 8 pad: conflict-free frag LDS + staging STS
#define BSTRIDE 72    // BN + 8 pad

template<bool USE_GH, bool GELU>
__global__ __launch_bounds__(256, 2)
void gemm_tf32(const float* __restrict__ Ain,
               const float* __restrict__ Bin,
               const float* __restrict__ bias)
{
    const float* A    = USE_GH ? (const float*)g_h : Ain;
    float*       Cout = GELU   ? g_h : g_q;

    const int bm = blockIdx.y * 128;
    const int bn = blockIdx.x * 64;

    __shared__ float As[2][16][ASTRIDE];
    __shared__ float Bs[2][16][BSTRIDE];

    const int tid  = threadIdx.x;
    const int w    = tid >> 5;
    const int lane = tid & 31;
    const int wm   = w & 3;          // 0..3 -> m offset wm*32
    const int wn   = w >> 2;         // 0..1 -> n offset wn*32
    const int g    = lane >> 2;      // group id 0..7
    const int tig  = lane & 3;       // thread-in-group 0..3

    // staging assignment (conflict-free STS)
    const int rowA = tid & 127;      // A row
    const int sA   = tid >> 7;       // 0/1 -> k offset sA*8
    const int rowB = tid & 63;       // B row
    const int sB   = tid >> 6;       // 0..3 -> k offset sB*4

    const float* Ap = A   + (size_t)(bm + rowA) * DIM + sA * 8;
    const float* Bp = Bin + (size_t)(bn + rowB) * DIM + sB * 4;

    float acc[2][4][4];
#pragma unroll
    for (int mt = 0; mt < 2; mt++)
#pragma unroll
        for (int nt = 0; nt < 4; nt++)
#pragma unroll
            for (int i = 0; i < 4; i++) acc[mt][nt][i] = 0.f;

    float4 ra0 = *(const float4*)(Ap);
    float4 ra1 = *(const float4*)(Ap + 4);
    float4 rb  = *(const float4*)(Bp);

#define STORE_TILE(BUF)                                                      \
    do {                                                                     \
        As[BUF][sA*8+0][rowA] = ra0.x; As[BUF][sA*8+1][rowA] = ra0.y;        \
        As[BUF][sA*8+2][rowA] = ra0.z; As[BUF][sA*8+3][rowA] = ra0.w;        \
        As[BUF][sA*8+4][rowA] = ra1.x; As[BUF][sA*8+5][rowA] = ra1.y;        \
        As[BUF][sA*8+6][rowA] = ra1.z; As[BUF][sA*8+7][rowA] = ra1.w;        \
        Bs[BUF][sB*4+0][rowB] = rb.x;  Bs[BUF][sB*4+1][rowB] = rb.y;         \
        Bs[BUF][sB*4+2][rowB] = rb.z;  Bs[BUF][sB*4+3][rowB] = rb.w;         \
    } while (0)

    STORE_TILE(0);
    __syncthreads();

    int buf = 0;
#pragma unroll 1
    for (int kt = 0; kt < DIM; kt += 16) {
        const bool more = (kt + 16) < DIM;
        if (more) {
            ra0 = *(const float4*)(Ap + kt + 16);
            ra1 = *(const float4*)(Ap + kt + 16 + 4);
            rb  = *(const float4*)(Bp + kt + 16);
        }

#pragma unroll
        for (int kk = 0; kk < 16; kk += 8) {
            // A fragments for both m-tiles: value (m, k)
            uint32_t ah[2][4], al[2][4];
#pragma unroll
            for (int mt = 0; mt < 2; mt++) {
                const int m0 = wm * 32 + mt * 16;
                float f0 = As[buf][kk + tig][m0 + g];
                float f1 = As[buf][kk + tig][m0 + g + 8];
                float f2 = As[buf][kk + tig + 4][m0 + g];
                float f3 = As[buf][kk + tig + 4][m0 + g + 8];
                split_tf32(f0, ah[mt][0], al[mt][0]);
                split_tf32(f1, ah[mt][1], al[mt][1]);
                split_tf32(f2, ah[mt][2], al[mt][2]);
                split_tf32(f3, ah[mt][3], al[mt][3]);
            }
#pragma unroll
            for (int nt = 0; nt < 4; nt++) {
                const int n0 = wn * 32 + nt * 8;
                float fb0 = Bs[buf][kk + tig][n0 + g];
                float fb1 = Bs[buf][kk + tig + 4][n0 + g];
                uint32_t bh0, bl0, bh1, bl1;
                split_tf32(fb0, bh0, bl0);
                split_tf32(fb1, bh1, bl1);
#pragma unroll
                for (int mt = 0; mt < 2; mt++) {
                    float* d = acc[mt][nt];
                    mma_tf32(d, al[mt][0], al[mt][1], al[mt][2], al[mt][3], bh0, bh1);
                    mma_tf32(d, ah[mt][0], ah[mt][1], ah[mt][2], ah[mt][3], bl0, bl1);
                    mma_tf32(d, ah[mt][0], ah[mt][1], ah[mt][2], ah[mt][3], bh0, bh1);
                }
            }
        }

        if (more) {
            buf ^= 1;
            STORE_TILE(buf);
            __syncthreads();
        }
    }
#undef STORE_TILE

    // fused epilogue: bias (+GELU), write fp32
#pragma unroll
    for (int mt = 0; mt < 2; mt++) {
        const int r0 = bm + wm * 32 + mt * 16 + g;
#pragma unroll
        for (int nt = 0; nt < 4; nt++) {
            const int c0 = bn + wn * 32 + nt * 8 + 2 * tig;
            const float2 bb = *(const float2*)&bias[c0];
            float2 v0, v1;
            v0.x = acc[mt][nt][0] + bb.x;
            v0.y = acc[mt][nt][1] + bb.y;
            v1.x = acc[mt][nt][2] + bb.x;
            v1.y = acc[mt][nt][3] + bb.y;
            if (GELU) {
                v0.x = gelu_exact(v0.x); v0.y = gelu_exact(v0.y);
                v1.x = gelu_exact(v1.x); v1.y = gelu_exact(v1.y);
            }
            *(float2*)&Cout[(size_t)r0 * DIM + c0]       = v0;
            *(float2*)&Cout[(size_t)(r0 + 8) * DIM + c0] = v1;
        }
    }
}

// =========================================================================
// Fused gather + scores + softmax + recombine (single HBM pass per row).
// One block per batch row b. 8 warps, each owns 16 keys with a private
// online-softmax state (m, s, y[1024] in registers); merged via smem.
// NOTE: Kset arrives as int32 (JAX x64 disabled downgrades int64->int32).
// =========================================================================
__global__ __launch_bounds__(256)
void attn_kernel(const float* __restrict__ mem,
                 const int* __restrict__ kset,
                 float* __restrict__ p_out,
                 float* __restrict__ y_out)
{
    const int b    = blockIdx.x;
    const int tid  = threadIdx.x;
    const int w    = tid >> 5;
    const int lane = tid & 31;

    __shared__ float s_scores[KSET];
    __shared__ float s_m[8];
    __shared__ float s_s[8];
    __shared__ float s_y[8][DIM];   // 32 KB

    // query row in registers: element layout (lane + 32*j) per float4 slot
    const float4* qv = (const float4*)(g_q + (size_t)b * DIM);
    float4 qr[8];
#pragma unroll
    for (int j = 0; j < 8; j++) qr[j] = qv[lane + 32 * j];

    float m = -INFINITY, s = 0.f;
    float4 y[8];
#pragma unroll
    for (int j = 0; j < 8; j++) y[j] = make_float4(0.f, 0.f, 0.f, 0.f);

    const int* krow = kset + (size_t)b * KSET;

#pragma unroll 1
    for (int i = 0; i < 16; i++) {
        const int k = w * 16 + i;
        int idx = krow[k];
        idx = min(max(idx, 0), N_MEM - 1);   // defensive clamp
        const float4* rv = (const float4*)(mem + (size_t)idx * DIM);

        float4 r[8];
#pragma unroll
        for (int j = 0; j < 8; j++) r[j] = rv[lane + 32 * j];

        float part = 0.f;
#pragma unroll
        for (int j = 0; j < 8; j++) {
            part = fmaf(r[j].x, qr[j].x, part);
            part = fmaf(r[j].y, qr[j].y, part);
            part = fmaf(r[j].z, qr[j].z, part);
            part = fmaf(r[j].w, qr[j].w, part);
        }
#pragma unroll
        for (int o = 16; o > 0; o >>= 1)
            part += __shfl_xor_sync(0xFFFFFFFFu, part, o);

        if (lane == 0) s_scores[k] = part;

        const float mn    = fmaxf(m, part);
        const float scale = __expf(m - mn);
        const float e     = __expf(part - mn);
        s = s * scale + e;
#pragma unroll
        for (int j = 0; j < 8; j++) {
            y[j].x = fmaf(y[j].x, scale, e * r[j].x);
            y[j].y = fmaf(y[j].y, scale, e * r[j].y);
            y[j].z = fmaf(y[j].z, scale, e * r[j].z);
            y[j].w = fmaf(y[j].w, scale, e * r[j].w);
        }
        m = mn;
    }

    if (lane == 0) { s_m[w] = m; s_s[w] = s; }
    __syncthreads();

    float M = -INFINITY;
#pragma unroll
    for (int w2 = 0; w2 < 8; w2++) M = fmaxf(M, s_m[w2]);
    float S = 0.f;
#pragma unroll
    for (int w2 = 0; w2 < 8; w2++) S += s_s[w2] * __expf(s_m[w2] - M);
    const float invS = 1.f / S;

    const float f = __expf(m - M);
    float4* ys = (float4*)s_y[w];
#pragma unroll
    for (int j = 0; j < 8; j++) {
        float4 v = y[j];
        v.x *= f; v.y *= f; v.z *= f; v.w *= f;
        ys[lane + 32 * j] = v;
    }
    __syncthreads();

    {
        float4 acc = make_float4(0.f, 0.f, 0.f, 0.f);
#pragma unroll
        for (int w2 = 0; w2 < 8; w2++) {
            float4 v = ((const float4*)s_y[w2])[tid];
            acc.x += v.x; acc.y += v.y; acc.z += v.z; acc.w += v.w;
        }
        acc.x *= invS; acc.y *= invS; acc.z *= invS; acc.w *= invS;
        ((float4*)(y_out + (size_t)b * DIM))[tid] = acc;
    }

    if (tid < KSET)
        p_out[(size_t)b * KSET + tid] = __expf(s_scores[tid] - M) * invS;
}

// =========================================================================
// Launch: GEMM1(fused GELU->g_h) -> GEMM2(fused bias->g_q) -> attention
// Output layout: P0 [B,K] flattened first, then Y0 [B,D].
// kernel_launch contains ONLY kernel launches (graph-capture safe).
// =========================================================================
extern "C" void kernel_launch(void* const* d_in, const int* in_sizes, int n_in,
                              void* d_out, int out_size)
{
    const float* emb  = (const float*)d_in[0];
    const float* mem  = (const float*)d_in[1];
    const int*   kset = (const int*)d_in[2];
    const float* W1   = (const float*)d_in[3];
    const float* b1   = (const float*)d_in[4];
    const float* W2   = (const float*)d_in[5];
    const float* b2   = (const float*)d_in[6];

    float* out   = (float*)d_out;
    float* p_out = out;                    // [B, K]
    float* y_out = out + BATCH * KSET;     // [B, D]

    dim3 ggrid(16, 8);   // (N/64, M/128)

    gemm_tf32<false, true ><<<ggrid, 256>>>(emb, W1, b1);
    gemm_tf32<true,  false><<<ggrid, 256>>>(nullptr, W2, b2);
    attn_kernel<<<BATCH, 256>>>(mem, kset, p_out, y_out);
}